// round 15
// baseline (speedup 1.0000x reference)
#include <cuda_runtime.h>
#include <cuda_fp16.h>
#include <cstdint>
#include <math.h>

// ---------------- problem dims ----------------
#define BATCH 8
#define CCH   512
#define NQ    4096
#define TLEN  256
#define CDIM  768
#define HID   512
#define NHEAD 8
#define DHEAD 64

// ---------------- scratch ----------------
__device__ __half g_xh  [(long)BATCH * CCH * NQ];
__device__ __half g_ctxh[(long)BATCH * TLEN * CDIM];
__device__ __half g_Wqh [HID * CCH];
__device__ __half g_Wkvh[2 * HID * CDIM];
__device__ __half g_Wouth[CCH * HID];
__device__ __half g_q   [(long)BATCH * HID * NQ];        // [b][o][i]
__device__ __half g_kv  [(long)BATCH * 2 * HID * TLEN];  // [b][o][t]
__device__ __half g_out [(long)BATCH * NQ * HID];        // [b][i][hd]

__device__ __forceinline__ uint32_t smem_u32(const void* p) {
    uint32_t a;
    asm("{ .reg .u64 t; cvta.to.shared.u64 t, %1; cvt.u32.u64 %0, t; }" : "=r"(a) : "l"(p));
    return a;
}
__device__ __forceinline__ uint32_t h2(float a, float b) {
    __half2 h = __floats2half2_rn(a, b);
    return *(uint32_t*)&h;
}
__device__ __forceinline__ void cpa16(uint32_t dst, const void* src) {
    asm volatile("cp.async.cg.shared.global [%0], [%1], 16;" :: "r"(dst), "l"(src));
}
#define CP_COMMIT() asm volatile("cp.async.commit_group;" ::: "memory")
template<int N> __device__ __forceinline__ void cp_wait() {
    asm volatile("cp.async.wait_group %0;" :: "n"(N) : "memory");
}
__device__ __forceinline__ void ldsm4(uint32_t* r, uint32_t addr) {
    asm volatile("ldmatrix.sync.aligned.m8n8.x4.shared.b16 {%0,%1,%2,%3}, [%4];"
                 : "=r"(r[0]), "=r"(r[1]), "=r"(r[2]), "=r"(r[3]) : "r"(addr));
}
__device__ __forceinline__ void ldsm4t(uint32_t* r, uint32_t addr) {
    asm volatile("ldmatrix.sync.aligned.m8n8.x4.trans.shared.b16 {%0,%1,%2,%3}, [%4];"
                 : "=r"(r[0]), "=r"(r[1]), "=r"(r[2]), "=r"(r[3]) : "r"(addr));
}
__device__ __forceinline__ void mma_f16(float* d, const uint32_t* a, const uint32_t* b) {
    asm volatile(
        "mma.sync.aligned.m16n8k16.row.col.f32.f16.f16.f32 "
        "{%0,%1,%2,%3}, {%4,%5,%6,%7}, {%8,%9}, {%0,%1,%2,%3};"
        : "+f"(d[0]), "+f"(d[1]), "+f"(d[2]), "+f"(d[3])
        : "r"(a[0]), "r"(a[1]), "r"(a[2]), "r"(a[3]), "r"(b[0]), "r"(b[1]));
}

// ---------------- merged fp32 -> fp16 conversion (1 launch) ----------------
struct F2HSeg { const float4* in; uint2* out; long n4; };
struct F2HArgs { F2HSeg seg[5]; long total4; };

__global__ __launch_bounds__(256) void f2h_all(F2HArgs args)
{
    long stride = (long)gridDim.x * 256;
    for (long i = (long)blockIdx.x * 256 + threadIdx.x; i < args.total4; i += stride) {
        long o = i;
        #pragma unroll
        for (int s = 0; s < 5; s++) {
            if (o < args.seg[s].n4) {
                float4 v = args.seg[s].in[o];
                args.seg[s].out[o] = make_uint2(h2(v.x, v.y), h2(v.z, v.w));
                break;
            }
            o -= args.seg[s].n4;
        }
    }
}

// =====================================================================
// fp16 mma GEMM: CTA 128x128, 128 threads (4 warps, 2x2), warp tile
// 64x64, BK=32, 3-stage cp.async, 2 CTAs/SM (two barrier domains).
//   C[z][m][n] = alpha * A[m][k] * B(k,n) (+ bias[m])
// A[m][k] k-contig. BDIR=1: B[n][k] k-contig. BDIR=0: B[k][n] n-contig.
// =====================================================================
template<int BDIR, typename CT>
__global__ __launch_bounds__(128, 2) void hgemm(
    const __half* __restrict__ A, const __half* __restrict__ B,
    CT* __restrict__ C, const float* __restrict__ bias,
    int lda, int ldb, int ldc, int kTotal,
    long sB1, long sC1, float alpha)
{
    constexpr int BM = 128, BN = 128, BK = 32;
    constexpr int AS = BK + 8;
    constexpr int BS = BDIR ? (BK + 8) : (BN + 8);
    constexpr int BROWS = BDIR ? BN : BK;
    constexpr int ASTG = BM * AS;
    constexpr int BSTG = BROWS * BS;

    extern __shared__ __half sm[];
    __half* Asm = sm;
    __half* Bsm = sm + 3 * ASTG;

    const int z = blockIdx.z;
    B += (long)z * sB1;
    C += (long)z * sC1;

    const int tid = threadIdx.x;
    const int wid = tid >> 5, lane = tid & 31;
    const int wm = wid & 1, wn = wid >> 1;       // 2 x 2 warp grid
    const int g = lane >> 2, t4 = lane & 3;
    const int l8 = lane & 7, l16 = lane & 15;
    const int lhi8 = (lane >> 4) << 3;
    const int lq8 = ((lane >> 3) & 1) << 3;

    const int m0 = blockIdx.y * BM;
    const int n0 = blockIdx.x * BN;
    const int mb = wm * 64, nb = wn * 64;

    const uint32_t Aaddr = smem_u32(Asm);
    const uint32_t Baddr = smem_u32(Bsm);

    float acc[4][8][4];
    #pragma unroll
    for (int i = 0; i < 4; i++)
        #pragma unroll
        for (int j = 0; j < 8; j++)
            #pragma unroll
            for (int r = 0; r < 4; r++) acc[i][j][r] = 0.0f;

    auto LOADS = [&](int s, int k0) {
        uint32_t ab = Aaddr + s * (ASTG * 2);
        uint32_t bb = Baddr + s * (BSTG * 2);
        #pragma unroll
        for (int r = 0; r < 4; r++) {
            int f = r * 128 + tid;
            int k8 = f & 3, m = f >> 2;
            cpa16(ab + (m * AS + k8 * 8) * 2, A + (long)(m0 + m) * lda + k0 + k8 * 8);
        }
        #pragma unroll
        for (int r = 0; r < 4; r++) {
            int f = r * 128 + tid;
            if (BDIR) {
                int k8 = f & 3, n = f >> 2;
                cpa16(bb + (n * BS + k8 * 8) * 2, B + (long)(n0 + n) * ldb + k0 + k8 * 8);
            } else {
                int n8 = f & 15, kk = f >> 4;
                cpa16(bb + (kk * BS + n8 * 8) * 2, B + (long)(k0 + kk) * ldb + n0 + n8 * 8);
            }
        }
    };
    auto COMPUTE = [&](int s) {
        const uint32_t ab = Aaddr + s * (ASTG * 2);
        const uint32_t bb = Baddr + s * (BSTG * 2);
        #pragma unroll
        for (int ks = 0; ks < 2; ks++) {
            const int kof = ks * 16;
            uint32_t a[4][4];
            #pragma unroll
            for (int mt = 0; mt < 4; mt++)
                ldsm4(a[mt], ab + ((mb + mt * 16 + l16) * AS + kof + lhi8) * 2);
            #pragma unroll
            for (int np = 0; np < 4; np++) {
                uint32_t b[4];
                if (BDIR)
                    ldsm4(b, bb + ((nb + np * 16 + lhi8 + l8) * BS + kof + lq8) * 2);
                else
                    ldsm4t(b, bb + ((kof + l16) * BS + nb + np * 16 + lhi8) * 2);
                #pragma unroll
                for (int mt = 0; mt < 4; mt++) {
                    mma_f16(acc[mt][np * 2],     a[mt], b);
                    mma_f16(acc[mt][np * 2 + 1], a[mt], b + 2);
                }
            }
        }
    };

    const int niter = kTotal / BK;
    LOADS(0, 0);
    CP_COMMIT();
    LOADS(1, BK);
    CP_COMMIT();
    cp_wait<1>();
    __syncthreads();

    for (int it = 0; it < niter; it++) {
        COMPUTE(it % 3);
        if (it + 2 < niter) {
            LOADS((it + 2) % 3, (it + 2) * BK);
            CP_COMMIT();
            cp_wait<1>();
        } else if (it + 1 < niter) {
            cp_wait<0>();
        }
        if (it + 1 < niter) __syncthreads();
    }

    #pragma unroll
    for (int mt = 0; mt < 4; mt++) {
        int m = m0 + mb + mt * 16 + g;
        float bv0 = bias ? bias[m] : 0.0f;
        float bv1 = bias ? bias[m + 8] : 0.0f;
        #pragma unroll
        for (int nt = 0; nt < 8; nt++) {
            int n = n0 + nb + nt * 8 + t4 * 2;
            if (sizeof(CT) == 4) {
                *(float2*)((float*)C + (long)m * ldc + n) =
                    make_float2(acc[mt][nt][0] * alpha + bv0, acc[mt][nt][1] * alpha + bv0);
                *(float2*)((float*)C + (long)(m + 8) * ldc + n) =
                    make_float2(acc[mt][nt][2] * alpha + bv1, acc[mt][nt][3] * alpha + bv1);
            } else {
                *(uint32_t*)((__half*)C + (long)m * ldc + n) =
                    h2(acc[mt][nt][0] * alpha + bv0, acc[mt][nt][1] * alpha + bv0);
                *(uint32_t*)((__half*)C + (long)(m + 8) * ldc + n) =
                    h2(acc[mt][nt][2] * alpha + bv1, acc[mt][nt][3] * alpha + bv1);
            }
        }
    }
}

// =====================================================================
// Fused attention (R14): 128 threads / 64-query tile, 2 CTAs/SM,
// register-resident P, __expf softmax without max-subtraction.
// =====================================================================
#define QS 72
#define KS 264
#define VS 264
#define OQ 0
#define OKk (OQ + 64 * QS)          // 4608
#define OV  (OKk + 64 * KS)         // 21504
#define FH_TOTAL (OV + 64 * VS)     // 38400 halves
#define ORS 66
#define RED_BYTES 1024
#define FSM_BYTES (FH_TOTAL * 2 + RED_BYTES)

__global__ __launch_bounds__(128, 2) void fused_attn(
    const __half* __restrict__ q, const __half* __restrict__ kv,
    __half* __restrict__ out)
{
    extern __shared__ __align__(16) char smraw[];
    __half* sh = (__half*)smraw;
    float* ored = (float*)smraw;
    float* reds = (float*)(smraw + FH_TOTAL * 2);

    const int z = blockIdx.y;
    const int b = z >> 3, h = z & 7;
    const int i0 = blockIdx.x * 64;
    const int tid = threadIdx.x;
    const int wid = tid >> 5, lane = tid & 31;
    const int wm = wid & 1, wn = wid >> 1;
    const int g = lane >> 2, t4 = lane & 3;
    const int l8 = lane & 7, l16 = lane & 15;
    const int lhi8 = (lane >> 4) << 3;
    const int lq8 = ((lane >> 3) & 1) << 3;

    const __half* qp = q + (long)(b * HID + h * DHEAD) * NQ;
    const __half* kp = kv + (long)(b * 2 * HID + h * DHEAD) * TLEN;
    const __half* vp = kp + (long)HID * TLEN;

    const uint32_t sbase = smem_u32(sh);

    #pragma unroll
    for (int r = 0; r < 4; r++) {
        int f = r * 128 + tid;
        int i8 = f & 7, d = f >> 3;
        cpa16(sbase + (OQ + d * QS + i8 * 8) * 2, qp + (long)d * NQ + i0 + i8 * 8);
    }
    #pragma unroll
    for (int r = 0; r < 16; r++) {
        int f = r * 128 + tid;
        int j8 = f & 31, d = f >> 5;
        cpa16(sbase + (OKk + d * KS + j8 * 8) * 2, kp + d * TLEN + j8 * 8);
        cpa16(sbase + (OV + d * VS + j8 * 8) * 2, vp + d * TLEN + j8 * 8);
    }
    CP_COMMIT();
    cp_wait<0>();
    __syncthreads();

    const int MB = wm * 32, NB = wn * 128;

    float acc[2][16][4];
    #pragma unroll
    for (int i = 0; i < 2; i++)
        #pragma unroll
        for (int j = 0; j < 16; j++)
            #pragma unroll
            for (int r = 0; r < 4; r++) acc[i][j][r] = 0.0f;

    #pragma unroll
    for (int ks = 0; ks < 4; ks++) {
        const int kof = ks * 16;
        uint32_t a[2][4];
        ldsm4t(a[0], sbase + (OQ + (kof + lhi8 + l8) * QS + MB + lq8) * 2);
        ldsm4t(a[1], sbase + (OQ + (kof + lhi8 + l8) * QS + MB + 16 + lq8) * 2);
        #pragma unroll
        for (int np = 0; np < 8; np++) {
            uint32_t bfr[4];
            ldsm4t(bfr, sbase + (OKk + (kof + l16) * KS + NB + np * 16 + lhi8) * 2);
            mma_f16(acc[0][np * 2],     a[0], bfr);
            mma_f16(acc[1][np * 2],     a[1], bfr);
            mma_f16(acc[0][np * 2 + 1], a[0], bfr + 2);
            mma_f16(acc[1][np * 2 + 1], a[1], bfr + 2);
        }
    }

    uint32_t pa[2][8][4];
    float rsm[2][2] = {};
    #pragma unroll
    for (int mt = 0; mt < 2; mt++) {
        #pragma unroll
        for (int c = 0; c < 8; c++) {
            float e00 = __expf(acc[mt][2 * c][0]);
            float e01 = __expf(acc[mt][2 * c][1]);
            float e02 = __expf(acc[mt][2 * c][2]);
            float e03 = __expf(acc[mt][2 * c][3]);
            float e10 = __expf(acc[mt][2 * c + 1][0]);
            float e11 = __expf(acc[mt][2 * c + 1][1]);
            float e12 = __expf(acc[mt][2 * c + 1][2]);
            float e13 = __expf(acc[mt][2 * c + 1][3]);
            rsm[mt][0] += e00 + e01 + e10 + e11;
            rsm[mt][1] += e02 + e03 + e12 + e13;
            pa[mt][c][0] = h2(e00, e01);
            pa[mt][c][1] = h2(e02, e03);
            pa[mt][c][2] = h2(e10, e11);
            pa[mt][c][3] = h2(e12, e13);
        }
    }
    #pragma unroll
    for (int mt = 0; mt < 2; mt++)
        #pragma unroll
        for (int u = 0; u < 2; u++) {
            float s = rsm[mt][u];
            s += __shfl_xor_sync(0xffffffffu, s, 1);
            s += __shfl_xor_sync(0xffffffffu, s, 2);
            if (t4 == 0) reds[wn * 64 + wm * 32 + mt * 16 + u * 8 + g] = s;
        }
    __syncthreads();
    float inv[2][2];
    #pragma unroll
    for (int mt = 0; mt < 2; mt++)
        #pragma unroll
        for (int u = 0; u < 2; u++) {
            int r = wm * 32 + mt * 16 + u * 8 + g;
            inv[mt][u] = 1.0f / (reds[r] + reds[64 + r]);
        }

    float acco[2][8][4];
    #pragma unroll
    for (int i = 0; i < 2; i++)
        #pragma unroll
        for (int j = 0; j < 8; j++)
            #pragma unroll
            for (int r = 0; r < 4; r++) acco[i][j][r] = 0.0f;

    #pragma unroll
    for (int c = 0; c < 8; c++) {
        const int kof = NB + c * 16;
        #pragma unroll
        for (int dt = 0; dt < 4; dt++) {
            uint32_t bfr[4];
            ldsm4(bfr, sbase + (OV + (dt * 16 + lhi8 + l8) * VS + kof + lq8) * 2);
            mma_f16(acco[0][dt * 2],     pa[0][c], bfr);
            mma_f16(acco[1][dt * 2],     pa[1][c], bfr);
            mma_f16(acco[0][dt * 2 + 1], pa[0][c], bfr + 2);
            mma_f16(acco[1][dt * 2 + 1], pa[1][c], bfr + 2);
        }
    }

    if (wn == 1) {
        #pragma unroll
        for (int mt = 0; mt < 2; mt++) {
            int row = MB + mt * 16 + g;
            #pragma unroll
            for (int nt = 0; nt < 8; nt++) {
                int d = nt * 8 + 2 * t4;
                *(float2*)&ored[row * ORS + d] =
                    make_float2(acco[mt][nt][0], acco[mt][nt][1]);
                *(float2*)&ored[(row + 8) * ORS + d] =
                    make_float2(acco[mt][nt][2], acco[mt][nt][3]);
            }
        }
    }
    __syncthreads();
    if (wn == 0) {
        __half* op = out + ((long)b * NQ + i0) * HID + h * DHEAD;
        #pragma unroll
        for (int mt = 0; mt < 2; mt++) {
            int row = MB + mt * 16 + g;
            #pragma unroll
            for (int nt = 0; nt < 8; nt++) {
                int d = nt * 8 + 2 * t4;
                float2 p0 = *(float2*)&ored[row * ORS + d];
                float2 p1 = *(float2*)&ored[(row + 8) * ORS + d];
                *(uint32_t*)(op + (long)row * HID + d) =
                    h2((acco[mt][nt][0] + p0.x) * inv[mt][0],
                       (acco[mt][nt][1] + p0.y) * inv[mt][0]);
                *(uint32_t*)(op + (long)(row + 8) * HID + d) =
                    h2((acco[mt][nt][2] + p1.x) * inv[mt][1],
                       (acco[mt][nt][3] + p1.y) * inv[mt][1]);
            }
        }
    }
}

// ================= launch =================
extern "C" void kernel_launch(void* const* d_in, const int* in_sizes, int n_in,
                              void* d_out, int out_size)
{
    const float* x    = (const float*)d_in[0];
    const float* ctx  = (const float*)d_in[1];
    const float* Wq   = (const float*)d_in[2];
    const float* Wkv  = (const float*)d_in[3];
    const float* Wout = (const float*)d_in[4];
    const float* bout = (const float*)d_in[5];
    float* y = (float*)d_out;

    __half *xh, *ctxh, *Wqh, *Wkvh, *Wouth, *q, *kv, *outb;
    cudaGetSymbolAddress((void**)&xh,    g_xh);
    cudaGetSymbolAddress((void**)&ctxh,  g_ctxh);
    cudaGetSymbolAddress((void**)&Wqh,   g_Wqh);
    cudaGetSymbolAddress((void**)&Wkvh,  g_Wkvh);
    cudaGetSymbolAddress((void**)&Wouth, g_Wouth);
    cudaGetSymbolAddress((void**)&q,     g_q);
    cudaGetSymbolAddress((void**)&kv,    g_kv);
    cudaGetSymbolAddress((void**)&outb,  g_out);

    constexpr int SM_B1 = 3 * (128 * 40 + 128 * 40) * 2;   // 61440
    constexpr int SM_B0 = 3 * (128 * 40 + 32 * 136) * 2;   // 56832

    cudaFuncSetAttribute((const void*)hgemm<0, __half>, cudaFuncAttributeMaxDynamicSharedMemorySize, SM_B0);
    cudaFuncSetAttribute((const void*)hgemm<1, __half>, cudaFuncAttributeMaxDynamicSharedMemorySize, SM_B1);
    cudaFuncSetAttribute((const void*)hgemm<1, float>,  cudaFuncAttributeMaxDynamicSharedMemorySize, SM_B1);
    cudaFuncSetAttribute((const void*)fused_attn,       cudaFuncAttributeMaxDynamicSharedMemorySize, FSM_BYTES);

    // 0) all fp32 -> fp16 conversions in ONE launch
    {
        F2HArgs a;
        a.seg[0] = { (const float4*)x,    (uint2*)xh,    (long)BATCH * CCH * NQ / 4 };
        a.seg[1] = { (const float4*)ctx,  (uint2*)ctxh,  (long)BATCH * TLEN * CDIM / 4 };
        a.seg[2] = { (const float4*)Wq,   (uint2*)Wqh,   (long)HID * CCH / 4 };
        a.seg[3] = { (const float4*)Wkv,  (uint2*)Wkvh,  (long)2 * HID * CDIM / 4 };
        a.seg[4] = { (const float4*)Wout, (uint2*)Wouth, (long)CCH * HID / 4 };
        a.total4 = a.seg[0].n4 + a.seg[1].n4 + a.seg[2].n4 + a.seg[3].n4 + a.seg[4].n4;
        f2h_all<<<148 * 8, 256>>>(a);
    }

    // 1) q = 0.125 * Wq @ x    (M=512,N=4096,K=512)/batch
    hgemm<0, __half><<<dim3(NQ / 128, CCH / 128, BATCH), 128, SM_B0>>>(
        Wqh, xh, q, nullptr, CCH, NQ, NQ, CCH,
        (long)CCH * NQ, (long)HID * NQ, 0.125f);

    // 2) kv = Wkv @ ctx^T      (M=1024,N=256,K=768)/batch
    hgemm<1, __half><<<dim3(TLEN / 128, (2 * HID) / 128, BATCH), 128, SM_B1>>>(
        Wkvh, ctxh, kv, nullptr, CDIM, CDIM, TLEN, CDIM,
        (long)TLEN * CDIM, (long)2 * HID * TLEN, 1.0f);

    // 3) fused attention (64-query tiles, 128 threads, 2 CTAs/SM)
    fused_attn<<<dim3(NQ / 64, BATCH * NHEAD), 128, FSM_BYTES>>>(q, kv, outb);

    // 4) y = Wout @ out + bout (M=512,N=4096,K=512)/batch
    hgemm<1, float><<<dim3(NQ / 128, CCH / 128, BATCH), 128, SM_B1>>>(
        Wouth, outb, y, bout, HID, HID, NQ, HID,
        (long)NQ * HID, (long)CCH * NQ, 1.0f);
}

// round 16
// speedup vs baseline: 1.0074x; 1.0074x over previous
#include <cuda_runtime.h>
#include <cuda_fp16.h>
#include <cstdint>
#include <math.h>

// ---------------- problem dims ----------------
#define BATCH 8
#define CCH   512
#define NQ    4096
#define TLEN  256
#define CDIM  768
#define HID   512
#define NHEAD 8
#define DHEAD 64

// ---------------- scratch ----------------
__device__ __half g_xh  [(long)BATCH * CCH * NQ];
__device__ __half g_ctxh[(long)BATCH * TLEN * CDIM];
__device__ __half g_Wqh [HID * CCH];
__device__ __half g_Wkvh[2 * HID * CDIM];
__device__ __half g_Wouth[CCH * HID];
__device__ __half g_q   [(long)BATCH * HID * NQ];        // [b][o][i]
__device__ __half g_kv  [(long)BATCH * 2 * HID * TLEN];  // [b][o][t]
__device__ __half g_out [(long)BATCH * NQ * HID];        // [b][i][hd]

__device__ __forceinline__ uint32_t smem_u32(const void* p) {
    uint32_t a;
    asm("{ .reg .u64 t; cvta.to.shared.u64 t, %1; cvt.u32.u64 %0, t; }" : "=r"(a) : "l"(p));
    return a;
}
__device__ __forceinline__ uint32_t h2(float a, float b) {
    __half2 h = __floats2half2_rn(a, b);
    return *(uint32_t*)&h;
}
__device__ __forceinline__ void cpa16(uint32_t dst, const void* src) {
    asm volatile("cp.async.cg.shared.global [%0], [%1], 16;" :: "r"(dst), "l"(src));
}
#define CP_COMMIT() asm volatile("cp.async.commit_group;" ::: "memory")
template<int N> __device__ __forceinline__ void cp_wait() {
    asm volatile("cp.async.wait_group %0;" :: "n"(N) : "memory");
}
__device__ __forceinline__ void ldsm4(uint32_t* r, uint32_t addr) {
    asm volatile("ldmatrix.sync.aligned.m8n8.x4.shared.b16 {%0,%1,%2,%3}, [%4];"
                 : "=r"(r[0]), "=r"(r[1]), "=r"(r[2]), "=r"(r[3]) : "r"(addr));
}
__device__ __forceinline__ void ldsm4t(uint32_t* r, uint32_t addr) {
    asm volatile("ldmatrix.sync.aligned.m8n8.x4.trans.shared.b16 {%0,%1,%2,%3}, [%4];"
                 : "=r"(r[0]), "=r"(r[1]), "=r"(r[2]), "=r"(r[3]) : "r"(addr));
}
__device__ __forceinline__ void mma_f16(float* d, const uint32_t* a, const uint32_t* b) {
    asm volatile(
        "mma.sync.aligned.m16n8k16.row.col.f32.f16.f16.f32 "
        "{%0,%1,%2,%3}, {%4,%5,%6,%7}, {%8,%9}, {%0,%1,%2,%3};"
        : "+f"(d[0]), "+f"(d[1]), "+f"(d[2]), "+f"(d[3])
        : "r"(a[0]), "r"(a[1]), "r"(a[2]), "r"(a[3]), "r"(b[0]), "r"(b[1]));
}

// ---------------- merged fp32 -> fp16 conversion (1 launch) ----------------
struct F2HSeg { const float4* in; uint2* out; long n4; };
struct F2HArgs { F2HSeg seg[5]; long total4; };

__global__ __launch_bounds__(256) void f2h_all(F2HArgs args)
{
    long stride = (long)gridDim.x * 256;
    for (long i = (long)blockIdx.x * 256 + threadIdx.x; i < args.total4; i += stride) {
        long o = i;
        #pragma unroll
        for (int s = 0; s < 5; s++) {
            if (o < args.seg[s].n4) {
                float4 v = args.seg[s].in[o];
                args.seg[s].out[o] = make_uint2(h2(v.x, v.y), h2(v.z, v.w));
                break;
            }
            o -= args.seg[s].n4;
        }
    }
}

// =====================================================================
// fp16 mma GEMM (R6/R14 config): CTA 128x128, warp tile 32x64, BK=32,
// 3-stage cp.async, 256 threads, 2 CTAs/SM.
// =====================================================================
template<int BDIR, typename CT>
__global__ __launch_bounds__(256, 2) void hgemm(
    const __half* __restrict__ A, const __half* __restrict__ B,
    CT* __restrict__ C, const float* __restrict__ bias,
    int lda, int ldb, int ldc, int kTotal,
    long sB1, long sC1, float alpha)
{
    constexpr int BM = 128, BN = 128, BK = 32;
    constexpr int AS = BK + 8;
    constexpr int BS = BDIR ? (BK + 8) : (BN + 8);
    constexpr int BROWS = BDIR ? BN : BK;
    constexpr int ASTG = BM * AS;
    constexpr int BSTG = BROWS * BS;

    extern __shared__ __half sm[];
    __half* Asm = sm;
    __half* Bsm = sm + 3 * ASTG;

    const int z = blockIdx.z;
    B += (long)z * sB1;
    C += (long)z * sC1;

    const int tid = threadIdx.x;
    const int wid = tid >> 5, lane = tid & 31;
    const int wm = wid & 3, wn = wid >> 2;
    const int g = lane >> 2, t4 = lane & 3;
    const int l8 = lane & 7, l16 = lane & 15;
    const int lhi8 = (lane >> 4) << 3;
    const int lq8 = ((lane >> 3) & 1) << 3;

    const int m0 = blockIdx.y * BM;
    const int n0 = blockIdx.x * BN;
    const int mb = wm * 32, nb = wn * 64;

    const uint32_t Aaddr = smem_u32(Asm);
    const uint32_t Baddr = smem_u32(Bsm);

    float acc[2][8][4];
    #pragma unroll
    for (int i = 0; i < 2; i++)
        #pragma unroll
        for (int j = 0; j < 8; j++)
            #pragma unroll
            for (int r = 0; r < 4; r++) acc[i][j][r] = 0.0f;

    auto LOADS = [&](int s, int k0) {
        uint32_t ab = Aaddr + s * (ASTG * 2);
        uint32_t bb = Baddr + s * (BSTG * 2);
        #pragma unroll
        for (int r = 0; r < 2; r++) {
            int f = r * 256 + tid;
            int k8 = f & 3, m = f >> 2;
            cpa16(ab + (m * AS + k8 * 8) * 2, A + (long)(m0 + m) * lda + k0 + k8 * 8);
        }
        #pragma unroll
        for (int r = 0; r < 2; r++) {
            int f = r * 256 + tid;
            if (BDIR) {
                int k8 = f & 3, n = f >> 2;
                cpa16(bb + (n * BS + k8 * 8) * 2, B + (long)(n0 + n) * ldb + k0 + k8 * 8);
            } else {
                int n8 = f & 15, kk = f >> 4;
                cpa16(bb + (kk * BS + n8 * 8) * 2, B + (long)(k0 + kk) * ldb + n0 + n8 * 8);
            }
        }
    };
    auto COMPUTE = [&](int s) {
        const uint32_t ab = Aaddr + s * (ASTG * 2);
        const uint32_t bb = Baddr + s * (BSTG * 2);
        #pragma unroll
        for (int ks = 0; ks < 2; ks++) {
            const int kof = ks * 16;
            uint32_t a[2][4];
            ldsm4(a[0], ab + ((mb + l16) * AS + kof + lhi8) * 2);
            ldsm4(a[1], ab + ((mb + 16 + l16) * AS + kof + lhi8) * 2);
            #pragma unroll
            for (int np = 0; np < 4; np++) {
                uint32_t b[4];
                if (BDIR)
                    ldsm4(b, bb + ((nb + np * 16 + lhi8 + l8) * BS + kof + lq8) * 2);
                else
                    ldsm4t(b, bb + ((kof + l16) * BS + nb + np * 16 + lhi8) * 2);
                mma_f16(acc[0][np * 2],     a[0], b);
                mma_f16(acc[1][np * 2],     a[1], b);
                mma_f16(acc[0][np * 2 + 1], a[0], b + 2);
                mma_f16(acc[1][np * 2 + 1], a[1], b + 2);
            }
        }
    };

    const int niter = kTotal / BK;
    LOADS(0, 0);
    CP_COMMIT();
    LOADS(1, BK);
    CP_COMMIT();
    cp_wait<1>();
    __syncthreads();

    for (int it = 0; it < niter; it++) {
        COMPUTE(it % 3);
        if (it + 2 < niter) {
            LOADS((it + 2) % 3, (it + 2) * BK);
            CP_COMMIT();
            cp_wait<1>();
        } else if (it + 1 < niter) {
            cp_wait<0>();
        }
        if (it + 1 < niter) __syncthreads();
    }

    #pragma unroll
    for (int mt = 0; mt < 2; mt++) {
        int m = m0 + mb + mt * 16 + g;
        float bv0 = bias ? bias[m] : 0.0f;
        float bv1 = bias ? bias[m + 8] : 0.0f;
        #pragma unroll
        for (int nt = 0; nt < 8; nt++) {
            int n = n0 + nb + nt * 8 + t4 * 2;
            if (sizeof(CT) == 4) {
                *(float2*)((float*)C + (long)m * ldc + n) =
                    make_float2(acc[mt][nt][0] * alpha + bv0, acc[mt][nt][1] * alpha + bv0);
                *(float2*)((float*)C + (long)(m + 8) * ldc + n) =
                    make_float2(acc[mt][nt][2] * alpha + bv1, acc[mt][nt][3] * alpha + bv1);
            } else {
                *(uint32_t*)((__half*)C + (long)m * ldc + n) =
                    h2(acc[mt][nt][0] * alpha + bv0, acc[mt][nt][1] * alpha + bv0);
                *(uint32_t*)((__half*)C + (long)(m + 8) * ldc + n) =
                    h2(acc[mt][nt][2] * alpha + bv1, acc[mt][nt][3] * alpha + bv1);
            }
        }
    }
}

// =====================================================================
// Fused attention: R14 design (128 threads / 64-query tile, 2 CTAs/SM,
// register-resident P) with the mid-kernel barrier removed:
// - ored gets its OWN smem region (no Q/K aliasing -> no WAR hazard)
// - inv computation deferred past PV; reds+ored covered by ONE barrier
// Barriers: 1 after loads, 1 before the final reduction. S->exp->PV is
// barrier-free per warp.
// =====================================================================
#define QS 72
#define KS 264
#define VS 264
#define OQ 0
#define OKk (OQ + 64 * QS)          // 4608
#define OV  (OKk + 64 * KS)         // 21504
#define FH_TOTAL (OV + 64 * VS)     // 38400 halves = 76800 B
#define ORS 66
#define RED_BYTES 1024
#define ORED_BYTES (64 * ORS * 4)   // 16896 B
#define FSM_BYTES (FH_TOTAL * 2 + RED_BYTES + ORED_BYTES)  // 94720 B

__global__ __launch_bounds__(128, 2) void fused_attn(
    const __half* __restrict__ q, const __half* __restrict__ kv,
    __half* __restrict__ out)
{
    extern __shared__ __align__(16) char smraw[];
    __half* sh = (__half*)smraw;
    float* reds = (float*)(smraw + FH_TOTAL * 2);               // [2][64]
    float* ored = (float*)(smraw + FH_TOTAL * 2 + RED_BYTES);   // [64][ORS]

    const int z = blockIdx.y;
    const int b = z >> 3, h = z & 7;
    const int i0 = blockIdx.x * 64;
    const int tid = threadIdx.x;
    const int wid = tid >> 5, lane = tid & 31;
    const int wm = wid & 1, wn = wid >> 1;
    const int g = lane >> 2, t4 = lane & 3;
    const int l8 = lane & 7, l16 = lane & 15;
    const int lhi8 = (lane >> 4) << 3;
    const int lq8 = ((lane >> 3) & 1) << 3;

    const __half* qp = q + (long)(b * HID + h * DHEAD) * NQ;
    const __half* kp = kv + (long)(b * 2 * HID + h * DHEAD) * TLEN;
    const __half* vp = kp + (long)HID * TLEN;

    const uint32_t sbase = smem_u32(sh);

    // ---- async loads: Q 64x64, K,V 64x256 (128 threads) ----
    #pragma unroll
    for (int r = 0; r < 4; r++) {
        int f = r * 128 + tid;
        int i8 = f & 7, d = f >> 3;
        cpa16(sbase + (OQ + d * QS + i8 * 8) * 2, qp + (long)d * NQ + i0 + i8 * 8);
    }
    #pragma unroll
    for (int r = 0; r < 16; r++) {
        int f = r * 128 + tid;
        int j8 = f & 31, d = f >> 5;
        cpa16(sbase + (OKk + d * KS + j8 * 8) * 2, kp + d * TLEN + j8 * 8);
        cpa16(sbase + (OV + d * VS + j8 * 8) * 2, vp + d * TLEN + j8 * 8);
    }
    CP_COMMIT();
    cp_wait<0>();
    __syncthreads();

    const int MB = wm * 32, NB = wn * 128;

    // ---- S = Q^T K : warp tile 32 x 128 ----
    float acc[2][16][4];
    #pragma unroll
    for (int i = 0; i < 2; i++)
        #pragma unroll
        for (int j = 0; j < 16; j++)
            #pragma unroll
            for (int r = 0; r < 4; r++) acc[i][j][r] = 0.0f;

    #pragma unroll
    for (int ks = 0; ks < 4; ks++) {
        const int kof = ks * 16;
        uint32_t a[2][4];
        ldsm4t(a[0], sbase + (OQ + (kof + lhi8 + l8) * QS + MB + lq8) * 2);
        ldsm4t(a[1], sbase + (OQ + (kof + lhi8 + l8) * QS + MB + 16 + lq8) * 2);
        #pragma unroll
        for (int np = 0; np < 8; np++) {
            uint32_t bfr[4];
            ldsm4t(bfr, sbase + (OKk + (kof + l16) * KS + NB + np * 16 + lhi8) * 2);
            mma_f16(acc[0][np * 2],     a[0], bfr);
            mma_f16(acc[1][np * 2],     a[1], bfr);
            mma_f16(acc[0][np * 2 + 1], a[0], bfr + 2);
            mma_f16(acc[1][np * 2 + 1], a[1], bfr + 2);
        }
    }

    // ---- exp in registers, pack PV A-frags, rowsum partials ----
    uint32_t pa[2][8][4];
    float rsm[2][2] = {};
    #pragma unroll
    for (int mt = 0; mt < 2; mt++) {
        #pragma unroll
        for (int c = 0; c < 8; c++) {
            float e00 = __expf(acc[mt][2 * c][0]);
            float e01 = __expf(acc[mt][2 * c][1]);
            float e02 = __expf(acc[mt][2 * c][2]);
            float e03 = __expf(acc[mt][2 * c][3]);
            float e10 = __expf(acc[mt][2 * c + 1][0]);
            float e11 = __expf(acc[mt][2 * c + 1][1]);
            float e12 = __expf(acc[mt][2 * c + 1][2]);
            float e13 = __expf(acc[mt][2 * c + 1][3]);
            rsm[mt][0] += e00 + e01 + e10 + e11;
            rsm[mt][1] += e02 + e03 + e12 + e13;
            pa[mt][c][0] = h2(e00, e01);
            pa[mt][c][1] = h2(e02, e03);
            pa[mt][c][2] = h2(e10, e11);
            pa[mt][c][3] = h2(e12, e13);
        }
    }
    // publish rowsum partials (visibility ensured by the post-PV barrier)
    #pragma unroll
    for (int mt = 0; mt < 2; mt++)
        #pragma unroll
        for (int u = 0; u < 2; u++) {
            float s = rsm[mt][u];
            s += __shfl_xor_sync(0xffffffffu, s, 1);
            s += __shfl_xor_sync(0xffffffffu, s, 2);
            if (t4 == 0) reds[wn * 64 + wm * 32 + mt * 16 + u * 8 + g] = s;
        }

    // ---- O_partial = P V (no barrier before; V region is read-only) ----
    float acco[2][8][4];
    #pragma unroll
    for (int i = 0; i < 2; i++)
        #pragma unroll
        for (int j = 0; j < 8; j++)
            #pragma unroll
            for (int r = 0; r < 4; r++) acco[i][j][r] = 0.0f;

    #pragma unroll
    for (int c = 0; c < 8; c++) {
        const int kof = NB + c * 16;
        #pragma unroll
        for (int dt = 0; dt < 4; dt++) {
            uint32_t bfr[4];
            ldsm4(bfr, sbase + (OV + (dt * 16 + lhi8 + l8) * VS + kof + lq8) * 2);
            mma_f16(acco[0][dt * 2],     pa[0][c], bfr);
            mma_f16(acco[1][dt * 2],     pa[1][c], bfr);
            mma_f16(acco[0][dt * 2 + 1], pa[0][c], bfr + 2);
            mma_f16(acco[1][dt * 2 + 1], pa[1][c], bfr + 2);
        }
    }

    // ---- wn==1 publishes partial O (own region, no aliasing) ----
    if (wn == 1) {
        #pragma unroll
        for (int mt = 0; mt < 2; mt++) {
            int row = MB + mt * 16 + g;
            #pragma unroll
            for (int nt = 0; nt < 8; nt++) {
                int d = nt * 8 + 2 * t4;
                *(float2*)&ored[row * ORS + d] =
                    make_float2(acco[mt][nt][0], acco[mt][nt][1]);
                *(float2*)&ored[(row + 8) * ORS + d] =
                    make_float2(acco[mt][nt][2], acco[mt][nt][3]);
            }
        }
    }
    __syncthreads();   // single barrier: reds + ored both visible

    if (wn == 0) {
        float inv[2][2];
        #pragma unroll
        for (int mt = 0; mt < 2; mt++)
            #pragma unroll
            for (int u = 0; u < 2; u++) {
                int r = wm * 32 + mt * 16 + u * 8 + g;
                inv[mt][u] = 1.0f / (reds[r] + reds[64 + r]);
            }
        __half* op = out + ((long)b * NQ + i0) * HID + h * DHEAD;
        #pragma unroll
        for (int mt = 0; mt < 2; mt++) {
            int row = MB + mt * 16 + g;
            #pragma unroll
            for (int nt = 0; nt < 8; nt++) {
                int d = nt * 8 + 2 * t4;
                float2 p0 = *(float2*)&ored[row * ORS + d];
                float2 p1 = *(float2*)&ored[(row + 8) * ORS + d];
                *(uint32_t*)(op + (long)row * HID + d) =
                    h2((acco[mt][nt][0] + p0.x) * inv[mt][0],
                       (acco[mt][nt][1] + p0.y) * inv[mt][0]);
                *(uint32_t*)(op + (long)(row + 8) * HID + d) =
                    h2((acco[mt][nt][2] + p1.x) * inv[mt][1],
                       (acco[mt][nt][3] + p1.y) * inv[mt][1]);
            }
        }
    }
}

// ================= launch =================
extern "C" void kernel_launch(void* const* d_in, const int* in_sizes, int n_in,
                              void* d_out, int out_size)
{
    const float* x    = (const float*)d_in[0];
    const float* ctx  = (const float*)d_in[1];
    const float* Wq   = (const float*)d_in[2];
    const float* Wkv  = (const float*)d_in[3];
    const float* Wout = (const float*)d_in[4];
    const float* bout = (const float*)d_in[5];
    float* y = (float*)d_out;

    __half *xh, *ctxh, *Wqh, *Wkvh, *Wouth, *q, *kv, *outb;
    cudaGetSymbolAddress((void**)&xh,    g_xh);
    cudaGetSymbolAddress((void**)&ctxh,  g_ctxh);
    cudaGetSymbolAddress((void**)&Wqh,   g_Wqh);
    cudaGetSymbolAddress((void**)&Wkvh,  g_Wkvh);
    cudaGetSymbolAddress((void**)&Wouth, g_Wouth);
    cudaGetSymbolAddress((void**)&q,     g_q);
    cudaGetSymbolAddress((void**)&kv,    g_kv);
    cudaGetSymbolAddress((void**)&outb,  g_out);

    constexpr int SM_B1 = 3 * (128 * 40 + 128 * 40) * 2;   // 61440
    constexpr int SM_B0 = 3 * (128 * 40 + 32 * 136) * 2;   // 56832

    cudaFuncSetAttribute((const void*)hgemm<0, __half>, cudaFuncAttributeMaxDynamicSharedMemorySize, SM_B0);
    cudaFuncSetAttribute((const void*)hgemm<1, __half>, cudaFuncAttributeMaxDynamicSharedMemorySize, SM_B1);
    cudaFuncSetAttribute((const void*)hgemm<1, float>,  cudaFuncAttributeMaxDynamicSharedMemorySize, SM_B1);
    cudaFuncSetAttribute((const void*)fused_attn,       cudaFuncAttributeMaxDynamicSharedMemorySize, FSM_BYTES);

    dim3 blk(256);

    // 0) all fp32 -> fp16 conversions in ONE launch
    {
        F2HArgs a;
        a.seg[0] = { (const float4*)x,    (uint2*)xh,    (long)BATCH * CCH * NQ / 4 };
        a.seg[1] = { (const float4*)ctx,  (uint2*)ctxh,  (long)BATCH * TLEN * CDIM / 4 };
        a.seg[2] = { (const float4*)Wq,   (uint2*)Wqh,   (long)HID * CCH / 4 };
        a.seg[3] = { (const float4*)Wkv,  (uint2*)Wkvh,  (long)2 * HID * CDIM / 4 };
        a.seg[4] = { (const float4*)Wout, (uint2*)Wouth, (long)CCH * HID / 4 };
        a.total4 = a.seg[0].n4 + a.seg[1].n4 + a.seg[2].n4 + a.seg[3].n4 + a.seg[4].n4;
        f2h_all<<<148 * 8, blk>>>(a);
    }

    // 1) q = 0.125 * Wq @ x    (M=512,N=4096,K=512)/batch
    hgemm<0, __half><<<dim3(NQ / 128, CCH / 128, BATCH), blk, SM_B0>>>(
        Wqh, xh, q, nullptr, CCH, NQ, NQ, CCH,
        (long)CCH * NQ, (long)HID * NQ, 0.125f);

    // 2) kv = Wkv @ ctx^T      (M=1024,N=256,K=768)/batch
    hgemm<1, __half><<<dim3(TLEN / 128, (2 * HID) / 128, BATCH), blk, SM_B1>>>(
        Wkvh, ctxh, kv, nullptr, CDIM, CDIM, TLEN, CDIM,
        (long)TLEN * CDIM, (long)2 * HID * TLEN, 1.0f);

    // 3) fused attention (64-query tiles, 128 threads, 2 CTAs/SM, 2 barriers)
    fused_attn<<<dim3(NQ / 64, BATCH * NHEAD), 128, FSM_BYTES>>>(q, kv, outb);

    // 4) y = Wout @ out + bout (M=512,N=4096,K=512)/batch
    hgemm<1, float><<<dim3(NQ / 128, CCH / 128, BATCH), blk, SM_B1>>>(
        Wouth, outb, y, bout, HID, HID, NQ, HID,
        (long)NQ * HID, (long)CCH * NQ, 1.0f);
}

// round 17
// speedup vs baseline: 1.0353x; 1.0277x over previous
#include <cuda_runtime.h>
#include <cuda_fp16.h>
#include <cstdint>
#include <math.h>

// ---------------- problem dims ----------------
#define BATCH 8
#define CCH   512
#define NQ    4096
#define TLEN  256
#define CDIM  768
#define HID   512
#define NHEAD 8
#define DHEAD 64

// ---------------- scratch ----------------
__device__ __half g_xh  [(long)BATCH * CCH * NQ];
__device__ __half g_ctxh[(long)BATCH * TLEN * CDIM];
__device__ __half g_Wqh [HID * CCH];
__device__ __half g_Wkvh[2 * HID * CDIM];
__device__ __half g_Wouth[CCH * HID];
__device__ __half g_q   [(long)BATCH * HID * NQ];        // [b][o][i]
__device__ __half g_kv  [(long)BATCH * 2 * HID * TLEN];  // [b][o][t]
__device__ __half g_out [(long)BATCH * NQ * HID];        // [b][i][hd]

__device__ __forceinline__ uint32_t smem_u32(const void* p) {
    uint32_t a;
    asm("{ .reg .u64 t; cvta.to.shared.u64 t, %1; cvt.u32.u64 %0, t; }" : "=r"(a) : "l"(p));
    return a;
}
__device__ __forceinline__ uint32_t h2(float a, float b) {
    __half2 h = __floats2half2_rn(a, b);
    return *(uint32_t*)&h;
}
__device__ __forceinline__ void cpa16(uint32_t dst, const void* src) {
    asm volatile("cp.async.cg.shared.global [%0], [%1], 16;" :: "r"(dst), "l"(src));
}
#define CP_COMMIT() asm volatile("cp.async.commit_group;" ::: "memory")
template<int N> __device__ __forceinline__ void cp_wait() {
    asm volatile("cp.async.wait_group %0;" :: "n"(N) : "memory");
}
__device__ __forceinline__ void ldsm4(uint32_t* r, uint32_t addr) {
    asm volatile("ldmatrix.sync.aligned.m8n8.x4.shared.b16 {%0,%1,%2,%3}, [%4];"
                 : "=r"(r[0]), "=r"(r[1]), "=r"(r[2]), "=r"(r[3]) : "r"(addr));
}
__device__ __forceinline__ void ldsm4t(uint32_t* r, uint32_t addr) {
    asm volatile("ldmatrix.sync.aligned.m8n8.x4.trans.shared.b16 {%0,%1,%2,%3}, [%4];"
                 : "=r"(r[0]), "=r"(r[1]), "=r"(r[2]), "=r"(r[3]) : "r"(addr));
}
__device__ __forceinline__ void mma_f16(float* d, const uint32_t* a, const uint32_t* b) {
    asm volatile(
        "mma.sync.aligned.m16n8k16.row.col.f32.f16.f16.f32 "
        "{%0,%1,%2,%3}, {%4,%5,%6,%7}, {%8,%9}, {%0,%1,%2,%3};"
        : "+f"(d[0]), "+f"(d[1]), "+f"(d[2]), "+f"(d[3])
        : "r"(a[0]), "r"(a[1]), "r"(a[2]), "r"(a[3]), "r"(b[0]), "r"(b[1]));
}

// ---------------- merged fp32 -> fp16 conversion (1 launch) ----------------
struct F2HSeg { const float4* in; uint2* out; long n4; };
struct F2HArgs { F2HSeg seg[5]; long total4; };

__global__ __launch_bounds__(256) void f2h_all(F2HArgs args)
{
    long stride = (long)gridDim.x * 256;
    for (long i = (long)blockIdx.x * 256 + threadIdx.x; i < args.total4; i += stride) {
        long o = i;
        #pragma unroll
        for (int s = 0; s < 5; s++) {
            if (o < args.seg[s].n4) {
                float4 v = args.seg[s].in[o];
                args.seg[s].out[o] = make_uint2(h2(v.x, v.y), h2(v.z, v.w));
                break;
            }
            o -= args.seg[s].n4;
        }
    }
}

// =====================================================================
// fp16 mma GEMM (R6/R14 config): CTA 128x128, warp tile 32x64, BK=32,
// 3-stage cp.async, 256 threads, 2 CTAs/SM.
// =====================================================================
template<int BDIR, typename CT>
__global__ __launch_bounds__(256, 2) void hgemm(
    const __half* __restrict__ A, const __half* __restrict__ B,
    CT* __restrict__ C, const float* __restrict__ bias,
    int lda, int ldb, int ldc, int kTotal,
    long sB1, long sC1, float alpha)
{
    constexpr int BM = 128, BN = 128, BK = 32;
    constexpr int AS = BK + 8;
    constexpr int BS = BDIR ? (BK + 8) : (BN + 8);
    constexpr int BROWS = BDIR ? BN : BK;
    constexpr int ASTG = BM * AS;
    constexpr int BSTG = BROWS * BS;

    extern __shared__ __half sm[];
    __half* Asm = sm;
    __half* Bsm = sm + 3 * ASTG;

    const int z = blockIdx.z;
    B += (long)z * sB1;
    C += (long)z * sC1;

    const int tid = threadIdx.x;
    const int wid = tid >> 5, lane = tid & 31;
    const int wm = wid & 3, wn = wid >> 2;
    const int g = lane >> 2, t4 = lane & 3;
    const int l8 = lane & 7, l16 = lane & 15;
    const int lhi8 = (lane >> 4) << 3;
    const int lq8 = ((lane >> 3) & 1) << 3;

    const int m0 = blockIdx.y * BM;
    const int n0 = blockIdx.x * BN;
    const int mb = wm * 32, nb = wn * 64;

    const uint32_t Aaddr = smem_u32(Asm);
    const uint32_t Baddr = smem_u32(Bsm);

    float acc[2][8][4];
    #pragma unroll
    for (int i = 0; i < 2; i++)
        #pragma unroll
        for (int j = 0; j < 8; j++)
            #pragma unroll
            for (int r = 0; r < 4; r++) acc[i][j][r] = 0.0f;

    auto LOADS = [&](int s, int k0) {
        uint32_t ab = Aaddr + s * (ASTG * 2);
        uint32_t bb = Baddr + s * (BSTG * 2);
        #pragma unroll
        for (int r = 0; r < 2; r++) {
            int f = r * 256 + tid;
            int k8 = f & 3, m = f >> 2;
            cpa16(ab + (m * AS + k8 * 8) * 2, A + (long)(m0 + m) * lda + k0 + k8 * 8);
        }
        #pragma unroll
        for (int r = 0; r < 2; r++) {
            int f = r * 256 + tid;
            if (BDIR) {
                int k8 = f & 3, n = f >> 2;
                cpa16(bb + (n * BS + k8 * 8) * 2, B + (long)(n0 + n) * ldb + k0 + k8 * 8);
            } else {
                int n8 = f & 15, kk = f >> 4;
                cpa16(bb + (kk * BS + n8 * 8) * 2, B + (long)(k0 + kk) * ldb + n0 + n8 * 8);
            }
        }
    };
    auto COMPUTE = [&](int s) {
        const uint32_t ab = Aaddr + s * (ASTG * 2);
        const uint32_t bb = Baddr + s * (BSTG * 2);
        #pragma unroll
        for (int ks = 0; ks < 2; ks++) {
            const int kof = ks * 16;
            uint32_t a[2][4];
            ldsm4(a[0], ab + ((mb + l16) * AS + kof + lhi8) * 2);
            ldsm4(a[1], ab + ((mb + 16 + l16) * AS + kof + lhi8) * 2);
            #pragma unroll
            for (int np = 0; np < 4; np++) {
                uint32_t b[4];
                if (BDIR)
                    ldsm4(b, bb + ((nb + np * 16 + lhi8 + l8) * BS + kof + lq8) * 2);
                else
                    ldsm4t(b, bb + ((kof + l16) * BS + nb + np * 16 + lhi8) * 2);
                mma_f16(acc[0][np * 2],     a[0], b);
                mma_f16(acc[1][np * 2],     a[1], b);
                mma_f16(acc[0][np * 2 + 1], a[0], b + 2);
                mma_f16(acc[1][np * 2 + 1], a[1], b + 2);
            }
        }
    };

    const int niter = kTotal / BK;
    LOADS(0, 0);
    CP_COMMIT();
    LOADS(1, BK);
    CP_COMMIT();
    cp_wait<1>();
    __syncthreads();

    for (int it = 0; it < niter; it++) {
        COMPUTE(it % 3);
        if (it + 2 < niter) {
            LOADS((it + 2) % 3, (it + 2) * BK);
            CP_COMMIT();
            cp_wait<1>();
        } else if (it + 1 < niter) {
            cp_wait<0>();
        }
        if (it + 1 < niter) __syncthreads();
    }

    #pragma unroll
    for (int mt = 0; mt < 2; mt++) {
        int m = m0 + mb + mt * 16 + g;
        float bv0 = bias ? bias[m] : 0.0f;
        float bv1 = bias ? bias[m + 8] : 0.0f;
        #pragma unroll
        for (int nt = 0; nt < 8; nt++) {
            int n = n0 + nb + nt * 8 + t4 * 2;
            if (sizeof(CT) == 4) {
                *(float2*)((float*)C + (long)m * ldc + n) =
                    make_float2(acc[mt][nt][0] * alpha + bv0, acc[mt][nt][1] * alpha + bv0);
                *(float2*)((float*)C + (long)(m + 8) * ldc + n) =
                    make_float2(acc[mt][nt][2] * alpha + bv1, acc[mt][nt][3] * alpha + bv1);
            } else {
                *(uint32_t*)((__half*)C + (long)m * ldc + n) =
                    h2(acc[mt][nt][0] * alpha + bv0, acc[mt][nt][1] * alpha + bv0);
                *(uint32_t*)((__half*)C + (long)(m + 8) * ldc + n) =
                    h2(acc[mt][nt][2] * alpha + bv1, acc[mt][nt][3] * alpha + bv1);
            }
        }
    }
}

// =====================================================================
// Fused attention, KV-chunked (2 x 128 tokens), register-resident P,
// no max-subtraction -> chunk partial sums add linearly (no rescaling).
// 128 threads (wm 0..1 x wn 0..1), 64-query tile, target 3 CTAs/SM.
// Smem: Q 64x64, K/V one 128-chunk at a time (reloaded per chunk),
// ored/reds own regions. ~62 KB.
// =====================================================================
#define QS 72
#define KS 136
#define VS 136
#define OQ 0
#define OKk (OQ + 64 * QS)           // 4608
#define OV  (OKk + 64 * KS)          // 13312
#define FH_TOTAL (OV + 64 * VS)      // 22016 halves = 44032 B
#define ORS 66
#define RED_BYTES 1024
#define ORED_BYTES (64 * ORS * 4)    // 16896 B
#define FSM_BYTES (FH_TOTAL * 2 + RED_BYTES + ORED_BYTES)  // 61952 B

__global__ __launch_bounds__(128, 3) void fused_attn(
    const __half* __restrict__ q, const __half* __restrict__ kv,
    __half* __restrict__ out)
{
    extern __shared__ __align__(16) char smraw[];
    __half* sh = (__half*)smraw;
    float* reds = (float*)(smraw + FH_TOTAL * 2);
    float* ored = (float*)(smraw + FH_TOTAL * 2 + RED_BYTES);

    const int z = blockIdx.y;
    const int b = z >> 3, h = z & 7;
    const int i0 = blockIdx.x * 64;
    const int tid = threadIdx.x;
    const int wid = tid >> 5, lane = tid & 31;
    const int wm = wid & 1, wn = wid >> 1;
    const int g = lane >> 2, t4 = lane & 3;
    const int l8 = lane & 7, l16 = lane & 15;
    const int lhi8 = (lane >> 4) << 3;
    const int lq8 = ((lane >> 3) & 1) << 3;

    const __half* qp = q + (long)(b * HID + h * DHEAD) * NQ;
    const __half* kp = kv + (long)(b * 2 * HID + h * DHEAD) * TLEN;
    const __half* vp = kp + (long)HID * TLEN;

    const uint32_t sbase = smem_u32(sh);

    // ---- load Q (persistent) + chunk 0 of K/V ----
    #pragma unroll
    for (int r = 0; r < 4; r++) {
        int f = r * 128 + tid;
        int i8 = f & 7, d = f >> 3;
        cpa16(sbase + (OQ + d * QS + i8 * 8) * 2, qp + (long)d * NQ + i0 + i8 * 8);
    }
    #pragma unroll
    for (int r = 0; r < 8; r++) {
        int f = r * 128 + tid;
        int j8 = f & 15, d = f >> 4;
        cpa16(sbase + (OKk + d * KS + j8 * 8) * 2, kp + d * TLEN + j8 * 8);
        cpa16(sbase + (OV + d * VS + j8 * 8) * 2, vp + d * TLEN + j8 * 8);
    }
    CP_COMMIT();
    cp_wait<0>();
    __syncthreads();

    const int MB = wm * 32, NB = wn * 64;   // NB within 128-chunk

    float acco[2][8][4];
    float rsm[2][2] = {};
    #pragma unroll
    for (int i = 0; i < 2; i++)
        #pragma unroll
        for (int j = 0; j < 8; j++)
            #pragma unroll
            for (int r = 0; r < 4; r++) acco[i][j][r] = 0.0f;

    #pragma unroll
    for (int ch = 0; ch < 2; ch++) {
        // ---- S = Q^T K_chunk : warp tile 32 x 64 ----
        float acc[2][8][4];
        #pragma unroll
        for (int i = 0; i < 2; i++)
            #pragma unroll
            for (int j = 0; j < 8; j++)
                #pragma unroll
                for (int r = 0; r < 4; r++) acc[i][j][r] = 0.0f;

        #pragma unroll
        for (int ks = 0; ks < 4; ks++) {
            const int kof = ks * 16;
            uint32_t a[2][4];
            ldsm4t(a[0], sbase + (OQ + (kof + lhi8 + l8) * QS + MB + lq8) * 2);
            ldsm4t(a[1], sbase + (OQ + (kof + lhi8 + l8) * QS + MB + 16 + lq8) * 2);
            #pragma unroll
            for (int np = 0; np < 4; np++) {
                uint32_t bfr[4];
                ldsm4t(bfr, sbase + (OKk + (kof + l16) * KS + NB + np * 16 + lhi8) * 2);
                mma_f16(acc[0][np * 2],     a[0], bfr);
                mma_f16(acc[1][np * 2],     a[1], bfr);
                mma_f16(acc[0][np * 2 + 1], a[0], bfr + 2);
                mma_f16(acc[1][np * 2 + 1], a[1], bfr + 2);
            }
        }

        // ---- exp -> PV A-frags (4 k16 chunks of this warp's 64 j) ----
        uint32_t pa[2][4][4];
        #pragma unroll
        for (int mt = 0; mt < 2; mt++) {
            #pragma unroll
            for (int c = 0; c < 4; c++) {
                float e00 = __expf(acc[mt][2 * c][0]);
                float e01 = __expf(acc[mt][2 * c][1]);
                float e02 = __expf(acc[mt][2 * c][2]);
                float e03 = __expf(acc[mt][2 * c][3]);
                float e10 = __expf(acc[mt][2 * c + 1][0]);
                float e11 = __expf(acc[mt][2 * c + 1][1]);
                float e12 = __expf(acc[mt][2 * c + 1][2]);
                float e13 = __expf(acc[mt][2 * c + 1][3]);
                rsm[mt][0] += e00 + e01 + e10 + e11;
                rsm[mt][1] += e02 + e03 + e12 + e13;
                pa[mt][c][0] = h2(e00, e01);
                pa[mt][c][1] = h2(e02, e03);
                pa[mt][c][2] = h2(e10, e11);
                pa[mt][c][3] = h2(e12, e13);
            }
        }

        // ---- PV accumulate: k = this warp's 64 j, n = all 64 d ----
        #pragma unroll
        for (int c = 0; c < 4; c++) {
            const int kof = NB + c * 16;
            #pragma unroll
            for (int dt = 0; dt < 4; dt++) {
                uint32_t bfr[4];
                ldsm4(bfr, sbase + (OV + (dt * 16 + lhi8 + l8) * VS + kof + lq8) * 2);
                mma_f16(acco[0][dt * 2],     pa[0][c], bfr);
                mma_f16(acco[1][dt * 2],     pa[1][c], bfr);
                mma_f16(acco[0][dt * 2 + 1], pa[0][c], bfr + 2);
                mma_f16(acco[1][dt * 2 + 1], pa[1][c], bfr + 2);
            }
        }

        // ---- reload K/V for next chunk (smem reuse needs barrier) ----
        if (ch == 0) {
            __syncthreads();
            #pragma unroll
            for (int r = 0; r < 8; r++) {
                int f = r * 128 + tid;
                int j8 = f & 15, d = f >> 4;
                cpa16(sbase + (OKk + d * KS + j8 * 8) * 2, kp + d * TLEN + 128 + j8 * 8);
                cpa16(sbase + (OV + d * VS + j8 * 8) * 2, vp + d * TLEN + 128 + j8 * 8);
            }
            CP_COMMIT();
            cp_wait<0>();
            __syncthreads();
        }
    }

    // ---- publish rowsums + partial O, one barrier, final reduce ----
    #pragma unroll
    for (int mt = 0; mt < 2; mt++)
        #pragma unroll
        for (int u = 0; u < 2; u++) {
            float s = rsm[mt][u];
            s += __shfl_xor_sync(0xffffffffu, s, 1);
            s += __shfl_xor_sync(0xffffffffu, s, 2);
            if (t4 == 0) reds[wn * 64 + wm * 32 + mt * 16 + u * 8 + g] = s;
        }
    if (wn == 1) {
        #pragma unroll
        for (int mt = 0; mt < 2; mt++) {
            int row = MB + mt * 16 + g;
            #pragma unroll
            for (int nt = 0; nt < 8; nt++) {
                int d = nt * 8 + 2 * t4;
                *(float2*)&ored[row * ORS + d] =
                    make_float2(acco[mt][nt][0], acco[mt][nt][1]);
                *(float2*)&ored[(row + 8) * ORS + d] =
                    make_float2(acco[mt][nt][2], acco[mt][nt][3]);
            }
        }
    }
    __syncthreads();
    if (wn == 0) {
        float inv[2][2];
        #pragma unroll
        for (int mt = 0; mt < 2; mt++)
            #pragma unroll
            for (int u = 0; u < 2; u++) {
                int r = wm * 32 + mt * 16 + u * 8 + g;
                inv[mt][u] = 1.0f / (reds[r] + reds[64 + r]);
            }
        __half* op = out + ((long)b * NQ + i0) * HID + h * DHEAD;
        #pragma unroll
        for (int mt = 0; mt < 2; mt++) {
            int row = MB + mt * 16 + g;
            #pragma unroll
            for (int nt = 0; nt < 8; nt++) {
                int d = nt * 8 + 2 * t4;
                float2 p0 = *(float2*)&ored[row * ORS + d];
                float2 p1 = *(float2*)&ored[(row + 8) * ORS + d];
                *(uint32_t*)(op + (long)row * HID + d) =
                    h2((acco[mt][nt][0] + p0.x) * inv[mt][0],
                       (acco[mt][nt][1] + p0.y) * inv[mt][0]);
                *(uint32_t*)(op + (long)(row + 8) * HID + d) =
                    h2((acco[mt][nt][2] + p1.x) * inv[mt][1],
                       (acco[mt][nt][3] + p1.y) * inv[mt][1]);
            }
        }
    }
}

// ================= launch =================
extern "C" void kernel_launch(void* const* d_in, const int* in_sizes, int n_in,
                              void* d_out, int out_size)
{
    const float* x    = (const float*)d_in[0];
    const float* ctx  = (const float*)d_in[1];
    const float* Wq   = (const float*)d_in[2];
    const float* Wkv  = (const float*)d_in[3];
    const float* Wout = (const float*)d_in[4];
    const float* bout = (const float*)d_in[5];
    float* y = (float*)d_out;

    __half *xh, *ctxh, *Wqh, *Wkvh, *Wouth, *q, *kv, *outb;
    cudaGetSymbolAddress((void**)&xh,    g_xh);
    cudaGetSymbolAddress((void**)&ctxh,  g_ctxh);
    cudaGetSymbolAddress((void**)&Wqh,   g_Wqh);
    cudaGetSymbolAddress((void**)&Wkvh,  g_Wkvh);
    cudaGetSymbolAddress((void**)&Wouth, g_Wouth);
    cudaGetSymbolAddress((void**)&q,     g_q);
    cudaGetSymbolAddress((void**)&kv,    g_kv);
    cudaGetSymbolAddress((void**)&outb,  g_out);

    constexpr int SM_B1 = 3 * (128 * 40 + 128 * 40) * 2;   // 61440
    constexpr int SM_B0 = 3 * (128 * 40 + 32 * 136) * 2;   // 56832

    cudaFuncSetAttribute((const void*)hgemm<0, __half>, cudaFuncAttributeMaxDynamicSharedMemorySize, SM_B0);
    cudaFuncSetAttribute((const void*)hgemm<1, __half>, cudaFuncAttributeMaxDynamicSharedMemorySize, SM_B1);
    cudaFuncSetAttribute((const void*)hgemm<1, float>,  cudaFuncAttributeMaxDynamicSharedMemorySize, SM_B1);
    cudaFuncSetAttribute((const void*)fused_attn,       cudaFuncAttributeMaxDynamicSharedMemorySize, FSM_BYTES);

    dim3 blk(256);

    // 0) all fp32 -> fp16 conversions in ONE launch
    {
        F2HArgs a;
        a.seg[0] = { (const float4*)x,    (uint2*)xh,    (long)BATCH * CCH * NQ / 4 };
        a.seg[1] = { (const float4*)ctx,  (uint2*)ctxh,  (long)BATCH * TLEN * CDIM / 4 };
        a.seg[2] = { (const float4*)Wq,   (uint2*)Wqh,   (long)HID * CCH / 4 };
        a.seg[3] = { (const float4*)Wkv,  (uint2*)Wkvh,  (long)2 * HID * CDIM / 4 };
        a.seg[4] = { (const float4*)Wout, (uint2*)Wouth, (long)CCH * HID / 4 };
        a.total4 = a.seg[0].n4 + a.seg[1].n4 + a.seg[2].n4 + a.seg[3].n4 + a.seg[4].n4;
        f2h_all<<<148 * 8, blk>>>(a);
    }

    // 1) q = 0.125 * Wq @ x    (M=512,N=4096,K=512)/batch
    hgemm<0, __half><<<dim3(NQ / 128, CCH / 128, BATCH), blk, SM_B0>>>(
        Wqh, xh, q, nullptr, CCH, NQ, NQ, CCH,
        (long)CCH * NQ, (long)HID * NQ, 0.125f);

    // 2) kv = Wkv @ ctx^T      (M=1024,N=256,K=768)/batch
    hgemm<1, __half><<<dim3(TLEN / 128, (2 * HID) / 128, BATCH), blk, SM_B1>>>(
        Wkvh, ctxh, kv, nullptr, CDIM, CDIM, TLEN, CDIM,
        (long)TLEN * CDIM, (long)2 * HID * TLEN, 1.0f);

    // 3) fused attention (KV-chunked, 64-query tiles, 128 threads, 3 CTAs/SM)
    fused_attn<<<dim3(NQ / 64, BATCH * NHEAD), 128, FSM_BYTES>>>(q, kv, outb);

    // 4) y = Wout @ out + bout (M=512,N=4096,K=512)/batch
    hgemm<1, float><<<dim3(NQ / 128, CCH / 128, BATCH), blk, SM_B1>>>(
        Wouth, outb, y, bout, HID, HID, NQ, HID,
        (long)NQ * HID, (long)CCH * NQ, 1.0f);
}